// round 2
// baseline (speedup 1.0000x reference)
#include <cuda_runtime.h>
#include <cuda_bf16.h>

// Problem constants
#define B_   4
#define S_   32
#define CIN  64
#define HID  64
#define COUT 128          // 2*HID
#define HH   32
#define WW   32
#define HWSZ 1024         // 32*32
#define FRAMES 128        // B*S
#define TOT_OUT 8388608   // B*S*HID*H*W

// Conv tiling
#define CCHUNK 8
#define OCB    16
#define ROWT   16         // rows per block (2 pixels per thread, spaced by 8)

// Scratch: conv output y [frame][oc][h][w] = 128*128*1024 floats = 64 MB
__device__ float g_y[(size_t)FRAMES * COUT * HWSZ];

__global__ __launch_bounds__(256) void conv_kernel(
    const float* __restrict__ x,
    const float* __restrict__ Wt,
    const float* __restrict__ bias)
{
    __shared__ float sIn[CCHUNK][ROWT + 2][WW + 2];   // 8*18*34 floats = 19.6 KB
    __shared__ float sW[OCB][CCHUNK][9];              // 16*8*9 = 4.6 KB

    const int f   = blockIdx.z;            // frame
    const int rt0 = blockIdx.y * ROWT;     // row-tile start
    const int oc0 = blockIdx.x * OCB;      // out-channel start
    const int tid = threadIdx.x;
    const int ty  = tid >> 5;              // 0..7
    const int tx  = tid & 31;              // 0..31

    float acc[OCB][2];
    #pragma unroll
    for (int o = 0; o < OCB; o++) { acc[o][0] = 0.f; acc[o][1] = 0.f; }

    const float* xf = x + (size_t)f * CIN * HWSZ;

    #pragma unroll 1
    for (int cc = 0; cc < CIN; cc += CCHUNK) {
        __syncthreads();
        // --- load input tile (with halo): 8*18*34 = 4896 elems, 20 strided steps ---
        {
            const int NELEM = CCHUNK * (ROWT + 2) * (WW + 2);   // 4896
            #pragma unroll
            for (int it = 0; it < (NELEM + 255) / 256; it++) {
                int i = it * 256 + tid;
                if (i < NELEM) {
                    int ci  = i / ((ROWT + 2) * (WW + 2));
                    int rem = i % ((ROWT + 2) * (WW + 2));
                    int rr  = rem / (WW + 2);
                    int col = rem % (WW + 2);
                    int gr  = rt0 + rr - 1;
                    int gc  = col - 1;
                    float v = 0.f;
                    if (gr >= 0 && gr < HH && gc >= 0 && gc < WW)
                        v = xf[(size_t)(cc + ci) * HWSZ + gr * WW + gc];
                    sIn[ci][rr][col] = v;
                }
            }
        }
        // --- load weights: 16*8*9 = 1152 elems, 5 strided steps ---
        {
            const int NW = OCB * CCHUNK * 9;                     // 1152
            #pragma unroll
            for (int it = 0; it < (NW + 255) / 256; it++) {
                int i = it * 256 + tid;
                if (i < NW) {
                    int o   = i / (CCHUNK * 9);
                    int rem = i % (CCHUNK * 9);
                    int ci  = rem / 9;
                    int k   = rem % 9;
                    sW[o][ci][k] = Wt[((size_t)(oc0 + o) * CIN + cc + ci) * 9 + k];
                }
            }
        }
        __syncthreads();

        #pragma unroll 1
        for (int ci = 0; ci < CCHUNK; ci++) {
            float xv[2][3][3];
            #pragma unroll
            for (int p = 0; p < 2; p++) {
                int rbase = ty + p * 8;
                #pragma unroll
                for (int dy = 0; dy < 3; dy++)
                    #pragma unroll
                    for (int dx = 0; dx < 3; dx++)
                        xv[p][dy][dx] = sIn[ci][rbase + dy][tx + dx];
            }
            #pragma unroll
            for (int o = 0; o < OCB; o++) {
                float w0 = sW[o][ci][0], w1 = sW[o][ci][1], w2 = sW[o][ci][2];
                float w3 = sW[o][ci][3], w4 = sW[o][ci][4], w5 = sW[o][ci][5];
                float w6 = sW[o][ci][6], w7 = sW[o][ci][7], w8 = sW[o][ci][8];
                #pragma unroll
                for (int p = 0; p < 2; p++) {
                    float a = acc[o][p];
                    a = fmaf(w0, xv[p][0][0], a);
                    a = fmaf(w1, xv[p][0][1], a);
                    a = fmaf(w2, xv[p][0][2], a);
                    a = fmaf(w3, xv[p][1][0], a);
                    a = fmaf(w4, xv[p][1][1], a);
                    a = fmaf(w5, xv[p][1][2], a);
                    a = fmaf(w6, xv[p][2][0], a);
                    a = fmaf(w7, xv[p][2][1], a);
                    a = fmaf(w8, xv[p][2][2], a);
                    acc[o][p] = a;
                }
            }
        }
    }

    // --- write y + bias ---
    #pragma unroll
    for (int o = 0; o < OCB; o++) {
        float bb = bias[oc0 + o];
        #pragma unroll
        for (int p = 0; p < 2; p++) {
            int r = rt0 + ty + p * 8;
            g_y[((size_t)f * COUT + oc0 + o) * HWSZ + r * WW + tx] = acc[o][p] + bb;
        }
    }
}

__device__ __forceinline__ float softplus_f(float v) {
    // log(1 + exp(v)), numerically stable
    return fmaxf(v, 0.f) + log1pf(expf(-fabsf(v)));
}

__global__ __launch_bounds__(256) void scan_kernel(
    const float* __restrict__ h0,
    float* __restrict__ out,
    float* __restrict__ hnext)
{
    int idx = blockIdx.x * blockDim.x + threadIdx.x;   // 0 .. B*HID*HW-1
    int hw = idx & (HWSZ - 1);
    int c  = (idx >> 10) & (HID - 1);
    int b  = idx >> 16;

    float a = 0.f;                                    // a_star running cumsum
    float L = logf(h0[((size_t)b * HID + c) * HWSZ + hw]);  // log_values[0] - a_star[0]

    const float* gp = g_y + (size_t)b * S_ * COUT * HWSZ + (size_t)c * HWSZ + hw;
    const float* hp = gp + (size_t)HID * HWSZ;
    float* ob = out + ((size_t)b * S_ * HID) * HWSZ + (size_t)c * HWSZ + hw;

    const size_t FSTRIDE = (size_t)COUT * HWSZ;   // y frame stride
    const size_t OSTRIDE = (size_t)HID * HWSZ;    // out frame stride

    float last = 0.f;
    #pragma unroll 1
    for (int s = 0; s < S_; s++) {
        float gate = *gp;
        float hid  = *hp;
        gp += FSTRIDE;
        hp += FSTRIDE;

        float logc = -softplus_f(gate);                  // -softplus(gate)
        float logz = -softplus_f(-gate);                 // -softplus(-gate)
        float lth  = (hid >= 0.f) ? logf(hid + 0.5f)     // log(relu(x)+0.5)
                                  : -softplus_f(-hid);   // -softplus(-x)

        a += logc;                                       // a_star[t]
        float v = logz + lth - a;                        // log_values[t] - a_star[t]

        // running logsumexp
        float mx = fmaxf(L, v);
        float mn = fminf(L, v);
        L = mx + log1pf(expf(mn - mx));

        float oh = expf(a + L);                          // exp(log_h[t])
        *ob = oh;
        ob += OSTRIDE;
        last = oh;
    }
    if (hnext)
        hnext[((size_t)b * HID + c) * HWSZ + hw] = last;
}

extern "C" void kernel_launch(void* const* d_in, const int* in_sizes, int n_in,
                              void* d_out, int out_size) {
    const float* x  = (const float*)d_in[0];
    const float* h0 = (const float*)d_in[1];
    const float* Wt = (const float*)d_in[2];
    const float* bv = (const float*)d_in[3];
    float* out = (float*)d_out;
    float* hnext = (out_size > TOT_OUT) ? out + TOT_OUT : nullptr;

    dim3 cgrid(COUT / OCB, HH / ROWT, FRAMES);   // (8, 2, 128)
    conv_kernel<<<cgrid, 256>>>(x, Wt, bv);

    int nthreads = B_ * HID * HWSZ;              // 262144
    scan_kernel<<<nthreads / 256, 256>>>(h0, out, hnext);
}